// round 14
// baseline (speedup 1.0000x reference)
#include <cuda_runtime.h>
#include <math_constants.h>

#define Dk 2048
#define Bk 32
#define LOG2E 1.4426950408889634f
#define KSPLIT 8
#define KCHUNK (Dk / KSPLIT)        // 256
#define NCOLS  64
#define XPAD   68                   // 272B rows: 16B-aligned, conflict-free

typedef unsigned long long u64;
typedef unsigned int u32;

// Scratch (no allocations allowed) -------------------------------------------
__device__ float  g_part[3 * KSPLIT * Dk * Bk];  // [mat][ks][col][b]
__device__ float  g_q2[Bk * Dk];   // (x@WqT + bq) * log2e
__device__ float  g_k [Bk * Dk];
__device__ float  g_v [Bk * Dk];
__device__ float4 g_kmp4[Bk * Dk / 2];           // pairs {k0,k1,m0,m1}
__device__ float4 g_c4 [Bk * Dk / 4];            // c packed 4-wide

__device__ __forceinline__ float ex2f(float x) {
    float r; asm("ex2.approx.f32 %0, %1;" : "=f"(r) : "f"(x)); return r;
}
__device__ __forceinline__ u64 pk2(float a, float b) {
    u64 r;
    asm("mov.b64 %0, {%1,%2};" : "=l"(r)
        : "r"(__float_as_uint(a)), "r"(__float_as_uint(b)));
    return r;
}
__device__ __forceinline__ void upk2f(u64 v, float &a, float &b) {
    u32 x, y;
    asm("mov.b64 {%0,%1}, %2;" : "=r"(x), "=r"(y) : "l"(v));
    a = __uint_as_float(x); b = __uint_as_float(y);
}
#define FMAX2(d,a,b,c) asm("fma.rn.f32x2 %0, %1, %2, %3;" : "=l"(d) : "l"(a), "l"(b), "l"(c))

// ---------------------------------------------------------------------------
// K1: split-K projection GEMM partials — packed FFMA2 along k (THIS ROUND'S
// ONLY CHANGE). Tiles/indexing/grid identical to R12.
// ---------------------------------------------------------------------------
__global__ __launch_bounds__(256, 1) void proj_kernel(
    const float* __restrict__ x,
    const float* __restrict__ Wq,
    const float* __restrict__ Wk,
    const float* __restrict__ Wv)
{
    __shared__ float xs[32 * XPAD];
    __shared__ float ws[NCOLS * XPAD];

    const int bx = blockIdx.x;
    const int mat = bx / (32 * KSPLIT);
    const int rem = bx % (32 * KSPLIT);
    const int colbase = (rem / KSPLIT) * NCOLS;
    const int ks  = rem % KSPLIT;
    const int k0base = ks * KCHUNK;

    const float* W = (mat == 0) ? Wq : (mat == 1) ? Wk : Wv;

    const int tid  = threadIdx.x;
    const int lane = tid & 31;           // batch
    const int wid  = tid >> 5;           // warp -> col group of 8

    u64 acc2[8];
    #pragma unroll
    for (int c = 0; c < 8; c++) acc2[c] = 0ull;

    for (int s = 0; s < KCHUNK / 64; s++) {
        const int k0 = k0base + s * 64;
        #pragma unroll
        for (int r = 0; r < 2; r++) {
            int idx = r * 256 + tid;
            int b = idx >> 4, kv = idx & 15;
            float4 t = *(const float4*)(x + b * Dk + k0 + kv * 4);
            *(float4*)(xs + b * XPAD + kv * 4) = t;
        }
        #pragma unroll
        for (int r = 0; r < 4; r++) {
            int idx = r * 256 + tid;
            int c = idx >> 4, kv = idx & 15;
            float4 t = *(const float4*)(W + (colbase + c) * Dk + k0 + kv * 4);
            *(float4*)(ws + c * XPAD + kv * 4) = t;
        }
        __syncthreads();

        const float* xrow  = xs + lane * XPAD;
        const float* wbase = ws + (wid * 8) * XPAD;

        #pragma unroll 4
        for (int k = 0; k < 64; k += 4) {
            double2 xv = *(const double2*)(xrow + k);     // 16B: (x0,x1),(x2,x3)
            u64 x01 = __double_as_longlong(xv.x);
            u64 x23 = __double_as_longlong(xv.y);
            #pragma unroll
            for (int c = 0; c < 8; c++) {
                double2 wv = *(const double2*)(wbase + c * XPAD + k);  // broadcast 16B
                u64 w01 = __double_as_longlong(wv.x);
                u64 w23 = __double_as_longlong(wv.y);
                FMAX2(acc2[c], x01, w01, acc2[c]);
                FMAX2(acc2[c], x23, w23, acc2[c]);
            }
        }
        __syncthreads();
    }

    float* dst = g_part + (((mat * KSPLIT + ks) * Dk) + colbase + wid * 8) * Bk + lane;
    #pragma unroll
    for (int c = 0; c < 8; c++) {
        float lo, hi; upk2f(acc2[c], lo, hi);
        dst[c * Bk] = lo + hi;
    }
}

// ---------------------------------------------------------------------------
// K1b: reduce over KSPLIT + bias + scale + transpose. UNCHANGED.
// ---------------------------------------------------------------------------
__global__ __launch_bounds__(256, 1) void reduce_kernel(
    const float* __restrict__ bq,
    const float* __restrict__ bk,
    const float* __restrict__ bv)
{
    __shared__ float s[NCOLS][33];

    const int mat = blockIdx.x / 32;
    const int colbase = (blockIdx.x % 32) * NCOLS;
    const int tid = threadIdx.x;

    const float* bias; float* out; float scale;
    if (mat == 0)      { bias = bq; out = g_q2; scale = LOG2E; }
    else if (mat == 1) { bias = bk; out = g_k;  scale = 1.0f; }
    else               { bias = bv; out = g_v;  scale = 1.0f; }

    const float* src = g_part + (mat * KSPLIT * Dk + colbase) * Bk;

    #pragma unroll
    for (int it = 0; it < 8; it++) {
        int e = it * 256 + tid;
        int c = e >> 5, b = e & 31;
        float sum = 0.f;
        #pragma unroll
        for (int p = 0; p < KSPLIT; p++)
            sum += src[p * Dk * Bk + c * Bk + b];
        s[c][b] = sum;
    }
    __syncthreads();

    #pragma unroll
    for (int it = 0; it < 8; it++) {
        int e = it * 256 + tid;
        int b = e >> 6, c = e & 63;
        out[b * Dk + colbase + c] = (s[c][b] + bias[colbase + c]) * scale;
    }
}

// ---------------------------------------------------------------------------
// K2 (pass1): UNCHANGED from R12.
// ---------------------------------------------------------------------------
__global__ __launch_bounds__(512, 3) void pass1_kernel()
{
    __shared__ float4 q2s4[Dk / 4];          // 8 KB
    __shared__ float wmx[16], wmn[16];
    __shared__ float partS[2][3][128];       // [chunk][iseg-1][jq]

    const int b    = blockIdx.y;
    const int tid  = threadIdx.x;
    const int jq   = tid & 127;
    const int iseg = tid >> 7;               // 0..3
    const float4* q2 = (const float4*)(g_q2 + b * Dk);

    float mx = -CUDART_INF_F, mn = CUDART_INF_F;
    {
        float4 v = q2[tid];
        q2s4[tid] = v;
        mx = fmaxf(fmaxf(v.x, v.y), fmaxf(v.z, v.w));
        mn = fminf(fminf(v.x, v.y), fminf(v.z, v.w));
    }
    #pragma unroll
    for (int o = 16; o; o >>= 1) {
        mx = fmaxf(mx, __shfl_xor_sync(0xffffffffu, mx, o));
        mn = fminf(mn, __shfl_xor_sync(0xffffffffu, mn, o));
    }
    if ((tid & 31) == 0) { wmx[tid >> 5] = mx; wmn[tid >> 5] = mn; }
    __syncthreads();
    mx = wmx[0]; mn = wmn[0];
    #pragma unroll
    for (int w = 1; w < 16; w++) {
        mx = fmaxf(mx, wmx[w]); mn = fminf(mn, wmn[w]);
    }

    const int i4base = iseg * 128;
    const double2* qp = (const double2*)(q2s4 + i4base);

    #pragma unroll 1
    for (int ch = 0; ch < 2; ch++) {
        const int j = blockIdx.x * 256 + ch * 128 + jq;

        const float kj    = g_k[b * Dk + j];
        const float negm2 = -((kj > 0.0f) ? mx : mn) * kj;   // exponent <= 0
        const u64 kk = pk2(kj, kj);
        const u64 mm = pk2(negm2, negm2);

        float a0 = 0.f, a1 = 0.f, a2 = 0.f, a3 = 0.f;
        #pragma unroll 2
        for (int i4 = 0; i4 < 128; i4++) {
            double2 qv = qp[i4];
            u64 q01 = __double_as_longlong(qv.x);
            u64 q23 = __double_as_longlong(qv.y);
            u64 e01, e23;
            FMAX2(e01, kk, q01, mm);
            FMAX2(e23, kk, q23, mm);
            float x0, x1, x2, x3;
            upk2f(e01, x0, x1); upk2f(e23, x2, x3);
            a0 += ex2f(x0);
            a1 += ex2f(x1);
            a2 += ex2f(x2);
            a3 += ex2f(x3);
        }
        float part = (a0 + a1) + (a2 + a3);

        if (iseg > 0) partS[ch][iseg - 1][jq] = part;
        __syncthreads();
        if (iseg == 0) {
            const float S = (part + partS[ch][0][jq]) +
                            (partS[ch][1][jq] + partS[ch][2][jq]);   // >= 1
            const float c = __fdividef(g_v[b * Dk + j], S);
            float* kmpf = (float*)g_kmp4;
            int base = (b * (Dk >> 1) + (j >> 1)) * 4 + (j & 1);
            kmpf[base]     = kj;
            kmpf[base + 2] = negm2;
            ((float*)g_c4)[b * Dk + j] = c;
        }
    }
}

// ---------------------------------------------------------------------------
// K3 (pass2): UNCHANGED from R12.
// ---------------------------------------------------------------------------
__global__ __launch_bounds__(512, 3) void pass2_kernel(float* __restrict__ out)
{
    __shared__ float4 kmps[Dk / 2];          // 16 KB {k0,k1,m0,m1} per 2 j
    __shared__ float4 cs[Dk / 4];            // 8 KB
    __shared__ float partO[2][3][128];       // [chunk][jseg-1][iq]

    const int b    = blockIdx.y;
    const int tid  = threadIdx.x;
    const int iq   = tid & 127;
    const int jseg = tid >> 7;               // 0..3

    const float4* kmsrc = g_kmp4 + b * (Dk / 2);
    const float4* csrc  = g_c4  + b * (Dk / 4);
    #pragma unroll
    for (int r = 0; r < 2; r++) kmps[r * 512 + tid] = kmsrc[r * 512 + tid];
    if (tid < Dk / 4) cs[tid] = csrc[tid];
    __syncthreads();

    const int jbase = jseg * 512;
    const double2* kmp = (const double2*)(kmps + (jbase >> 1));
    const float4*  cp  = cs + (jbase >> 2);

    #pragma unroll 1
    for (int ch = 0; ch < 2; ch++) {
        const int i = blockIdx.x * 256 + ch * 128 + iq;
        const float qi = g_q2[b * Dk + i];
        const u64 qq = pk2(qi, qi);

        float a0 = 0.f, a1 = 0.f, a2 = 0.f, a3 = 0.f;
        #pragma unroll 2
        for (int jj = 0; jj < 128; jj++) {   // 4 j per iter
            double2 km0 = kmp[jj * 2 + 0];
            double2 km1 = kmp[jj * 2 + 1];
            float4  c4  = cp[jj];
            u64 e01, e23;
            FMAX2(e01, qq, __double_as_longlong(km0.x), __double_as_longlong(km0.y));
            FMAX2(e23, qq, __double_as_longlong(km1.x), __double_as_longlong(km1.y));
            float x0, x1, x2, x3;
            upk2f(e01, x0, x1); upk2f(e23, x2, x3);
            a0 = fmaf(ex2f(x0), c4.x, a0);
            a1 = fmaf(ex2f(x1), c4.y, a1);
            a2 = fmaf(ex2f(x2), c4.z, a2);
            a3 = fmaf(ex2f(x3), c4.w, a3);
        }
        float part = (a0 + a1) + (a2 + a3);

        if (jseg > 0) partO[ch][jseg - 1][iq] = part;
        __syncthreads();
        if (jseg == 0)
            out[b * Dk + i] = (part + partO[ch][0][iq]) +
                              (partO[ch][1][iq] + partO[ch][2][iq]);
    }
}

// ---------------------------------------------------------------------------
extern "C" void kernel_launch(void* const* d_in, const int* in_sizes, int n_in,
                              void* d_out, int out_size)
{
    (void)in_sizes; (void)n_in; (void)out_size;
    const float* x  = (const float*)d_in[0];
    const float* Wq = (const float*)d_in[1];
    const float* bq = (const float*)d_in[2];
    const float* Wk = (const float*)d_in[3];
    const float* bk = (const float*)d_in[4];
    const float* Wv = (const float*)d_in[5];
    const float* bv = (const float*)d_in[6];
    float* out = (float*)d_out;

    proj_kernel<<<3 * 32 * KSPLIT, 256>>>(x, Wq, Wk, Wv);
    reduce_kernel<<<3 * 32, 256>>>(bq, bk, bv);

    dim3 grid_s(Dk / 256, Bk);   // (8, 32) = 256 blocks, single wave
    pass1_kernel<<<grid_s, 512>>>();
    pass2_kernel<<<grid_s, 512>>>(out);
}